// round 17
// baseline (speedup 1.0000x reference)
#include <cuda_runtime.h>
#include <math.h>

// ---------------------------------------------------------------------------
// R17: ONE kernel. All epilogue work executes WHILE the conv grid is full
// (the 16-round-invariant ~20us tail only appears for work run after the
// grid drains). Per-sample rendezvous: readout block n waits only for its
// own 20 images, which finish mid-kernel.
//  - blocks 0..15: readout for sample n (precompute overlaps conv; volatile
//    busy-poll on g_scnt[n]; chunked-float4 MLP).
//  - blocks 16..1727: R15 low-reg conv1 (one output/thread) + R11 last-
//    arriver conv2 per image -> g_feat -> bump g_scnt[img/20].
// ---------------------------------------------------------------------------

#define NIMG 320
#define H1S (3 * 1369)
#define TOTAL1 (NIMG * 1369)
#define NCONV 1712
#define NRD 16

__device__ float g_h1[NIMG * H1S];
__device__ float g_feat[NIMG * 6];
__device__ int g_imgcnt[NIMG];       // reset by consuming readout block
__device__ int g_scnt[16];           // reset by consuming readout block

__global__ __launch_bounds__(256, 4)
void fused_kernel(const float* __restrict__ nodes,
                  const float* __restrict__ pos,     // [16,5,4,6]
                  const float* __restrict__ attmap,  // [16,5,4,4]
                  const float* __restrict__ c1w, const float* __restrict__ c1b,
                  const float* __restrict__ c2w, const float* __restrict__ c2b,
                  const float* __restrict__ lw,  const float* __restrict__ lb,
                  const float* __restrict__ wfc_w, const float* __restrict__ wfc_b,
                  const float* __restrict__ fm_w,  const float* __restrict__ fm_b,
                  const float* __restrict__ lm_w,  const float* __restrict__ lm_b,
                  const float* __restrict__ fc1_w, const float* __restrict__ fc1_b,
                  const float* __restrict__ fc2_w, const float* __restrict__ fc2_b,
                  const float* __restrict__ fc3_w, const float* __restrict__ fc3_b,
                  float* __restrict__ out)           // [16,6]
{
    const int t = threadIdx.x;

    // ======================= READOUT BLOCKS (0..15) =========================
    if (blockIdx.x < NRD) {
        __shared__ float r_feat[20][6];
        __shared__ float r_ps[20][6];
        __shared__ float r_att[80];
        __shared__ float r_wfc[24];
        __shared__ float r_wb;
        __shared__ float r_asrc[20];
        __shared__ float r_btgt[20];
        __shared__ float r_pm[20][6];
        __shared__ float r_lmsg[20][6];
        __shared__ float r_inp[240];
        __shared__ float4 r_p4[8][30];
        __shared__ float4 r_p4b[4][15];
        __shared__ float r_r1[120];
        __shared__ float r_r2[60];

        const int n = blockIdx.x;

        // ---- pre-spin loads + pos-only precompute (overlap with conv) ----
        if (t < 120) {
            int fv = t / 6, d = t % 6;
            r_ps[fv][d] = pos[(n * 20 + fv) * 6 + d];
        }
        if (t >= 128 && t < 208) r_att[t - 128] = attmap[n * 80 + (t - 128)];
        if (t >= 208 && t < 232) r_wfc[t - 208] = wfc_w[t - 208];
        if (t == 232)            r_wb = wfc_b[0];
        __syncthreads();

        if (t < 20) {                        // pos part of edge logits
            float a = 0.0f, bb = 0.0f;
#pragma unroll
            for (int k = 0; k < 6; k++) {
                a  += r_ps[t][k] * r_wfc[6 + k];
                bb += r_ps[t][k] * r_wfc[18 + k];
            }
            r_asrc[t] = a;
            r_btgt[t] = bb;
        }
        if (t < 120) {                       // pm = pos @ fm_w + fm_b
            int fv = t / 6, d = t % 6;
            float s = __ldg(fm_b + d);
#pragma unroll
            for (int k = 0; k < 6; k++)
                s += r_ps[fv][k] * __ldg(fm_w + k * 6 + d);
            r_pm[fv][d] = s;
        }
        if (t >= 128 && t < 248) {           // last-frame message (pos-only)
            int tt = t - 128;
            int fv = tt / 6, d = tt % 6;
            int f = fv / 4, tv = fv % 4;
            float s = 0.0f;
            if (f > 0) {
                s = __ldg(lm_b + d);
#pragma unroll
                for (int k = 0; k < 6; k++)
                    s += r_ps[(f - 1) * 4 + tv][k] * __ldg(lm_w + k * 6 + d);
            }
            r_lmsg[fv][d] = s;
        }
        __syncthreads();

        // ---- busy-poll ONLY this sample's 20 producers (mid-kernel) ----
        if (t == 0) {
            while (((volatile int*)g_scnt)[n] < 20) {}
            __threadfence();                 // acquire g_feat
        }
        __syncthreads();

        if (t < 120) {
            int fv = t / 6, d = t % 6;
            r_feat[fv][d] = g_feat[(n * 20 + fv) * 6 + d];
        }
        __syncthreads();
        // reset this sample's counters for the next graph replay
        if (t == 0) g_scnt[n] = 0;
        if (t >= 32 && t < 52) g_imgcnt[n * 20 + (t - 32)] = 0;

        if (t < 20) {                        // finalize edge logits
            float a = r_asrc[t], bb = r_btgt[t];
#pragma unroll
            for (int k = 0; k < 6; k++) {
                a  += r_feat[t][k] * r_wfc[k];
                bb += r_feat[t][k] * r_wfc[12 + k];
            }
            r_asrc[t] = a;
            r_btgt[t] = bb;
        }
        __syncthreads();

        if (t < 120) {                       // aggregation + inp build
            int fv = t / 6, d = t % 6;
            int f = fv / 4, tv = fv % 4;
            float agg = r_lmsg[fv][d];
#pragma unroll
            for (int s = 0; s < 4; s++) {
                float z  = r_asrc[f * 4 + s] + r_btgt[f * 4 + tv] + r_wb;
                float lk = 1.0f / (1.0f + expf(-z));
                float m  = lk + r_att[f * 16 + s * 4 + tv];
                agg += m * r_pm[f * 4 + s][d];
            }
            r_inp[fv * 12 + d]     = r_feat[fv][d];
            r_inp[fv * 12 + 6 + d] = agg;
        }
        __syncthreads();

        if (t < 240) {                       // fc1: 8 chunks x 30 quads
            int c = t / 30, q = t - (t / 30) * 30;
            const float4* wrow = (const float4*)fc1_w;
            float4 a = make_float4(0.f, 0.f, 0.f, 0.f);
#pragma unroll
            for (int i = 0; i < 30; i++) {
                float  x = r_inp[c * 30 + i];
                float4 w = __ldg(wrow + (c * 30 + i) * 30 + q);
                a.x += x * w.x; a.y += x * w.y; a.z += x * w.z; a.w += x * w.w;
            }
            r_p4[c][q] = a;
        }
        __syncthreads();
        if (t < 120) {
            int q = t >> 2, comp = t & 3;
            float s = __ldg(fc1_b + t);
#pragma unroll
            for (int c = 0; c < 8; c++) {
                float4 p = r_p4[c][q];
                s += (comp == 0) ? p.x : (comp == 1) ? p.y
                     : (comp == 2) ? p.z : p.w;
            }
            r_r1[t] = fmaxf(s, 0.0f);
        }
        __syncthreads();

        if (t < 60) {                        // fc2: 4 chunks x 15 quads
            int c = t / 15, q = t - (t / 15) * 15;
            const float4* wrow = (const float4*)fc2_w;
            float4 a = make_float4(0.f, 0.f, 0.f, 0.f);
#pragma unroll
            for (int i = 0; i < 30; i++) {
                float  x = r_r1[c * 30 + i];
                float4 w = __ldg(wrow + (c * 30 + i) * 15 + q);
                a.x += x * w.x; a.y += x * w.y; a.z += x * w.z; a.w += x * w.w;
            }
            r_p4b[c][q] = a;
        }
        __syncthreads();
        if (t < 60) {
            int q = t >> 2, comp = t & 3;
            float s = __ldg(fc2_b + t);
#pragma unroll
            for (int c = 0; c < 4; c++) {
                float4 p = r_p4b[c][q];
                s += (comp == 0) ? p.x : (comp == 1) ? p.y
                     : (comp == 2) ? p.z : p.w;
            }
            r_r2[t] = fmaxf(s, 0.0f);
        }
        __syncthreads();

        if (t < 6) {
            float s = __ldg(fc3_b + t);
#pragma unroll
            for (int i = 0; i < 60; i++)
                s += r_r2[i] * __ldg(fc3_w + i * 6 + t);
            out[n * 6 + t] = s;
        }
        return;
    }

    // ======================= CONV BLOCKS (16..1727) =========================
    {
        __shared__ float sw[81];
        __shared__ float sb[3];
        __shared__ float sw2[27];
        __shared__ float s_conv[36][9];
        __shared__ float s_hs[36];
        __shared__ int   s_img[2];
        __shared__ int   s_do;

        if (t < 81) sw[t] = c1w[t];
        if (t < 3)  sb[t] = c1b[t];
        if (t >= 128 && t < 155) sw2[t - 128] = c2w[t - 128];
        __syncthreads();

        const int lo  = (blockIdx.x - NRD) * 256;
        const int idx = lo + t;

        if (idx < TOTAL1) {
            int px  = idx % 37;
            int rem = idx / 37;
            int py  = rem % 37;
            int img = rem / 37;

            const float* base = nodes + (size_t)img * 150528
                                      + (size_t)(6 * py) * 224 + 6 * px;
            float m0 = -1e30f, m1 = -1e30f, m2 = -1e30f;

#pragma unroll
            for (int cy = 0; cy < 3; cy++) {      // R15 low-reg slab form
                float a00 = sb[0], a01 = sb[1], a02 = sb[2];
                float a10 = sb[0], a11 = sb[1], a12 = sb[2];
                float a20 = sb[0], a21 = sb[1], a22 = sb[2];
#pragma unroll
                for (int ic = 0; ic < 3; ic++) {
                    const float* rp = base + ic * 50176 + (2 * cy) * 224;
                    float2 rr[3][4];
#pragma unroll
                    for (int r = 0; r < 3; r++)
#pragma unroll
                        for (int j = 0; j < 4; j++)
                            rr[r][j] = *(const float2*)(rp + r * 224 + 2 * j);
#pragma unroll
                    for (int ky = 0; ky < 3; ky++)
#pragma unroll
                        for (int kx = 0; kx < 3; kx++) {
                            float w0 = sw[ic * 9 + ky * 3 + kx];
                            float w1 = sw[27 + ic * 9 + ky * 3 + kx];
                            float w2 = sw[54 + ic * 9 + ky * 3 + kx];
                            int c0 = kx, c1 = 2 + kx, c2 = 4 + kx;
                            float v0 = (c0 & 1) ? rr[ky][c0 >> 1].y : rr[ky][c0 >> 1].x;
                            float v1 = (c1 & 1) ? rr[ky][c1 >> 1].y : rr[ky][c1 >> 1].x;
                            float v2 = (c2 & 1) ? rr[ky][c2 >> 1].y : rr[ky][c2 >> 1].x;
                            a00 += v0 * w0; a01 += v0 * w1; a02 += v0 * w2;
                            a10 += v1 * w0; a11 += v1 * w1; a12 += v1 * w2;
                            a20 += v2 * w0; a21 += v2 * w1; a22 += v2 * w2;
                        }
                }
                m0 = fmaxf(m0, fmaxf(a00, fmaxf(a10, a20)));
                m1 = fmaxf(m1, fmaxf(a01, fmaxf(a11, a21)));
                m2 = fmaxf(m2, fmaxf(a02, fmaxf(a12, a22)));
            }

            float* dst = g_h1 + (size_t)img * H1S + py * 37 + px;
            dst[0]        = fmaxf(m0, 0.0f);
            dst[1369]     = fmaxf(m1, 0.0f);
            dst[2 * 1369] = fmaxf(m2, 0.0f);
        }

        // publish h1; per-image counting; last arriver runs conv2 (overlapped)
        __threadfence();
        __syncthreads();
        if (t == 0) {
            int hi = (lo + 256 < TOTAL1) ? lo + 256 : TOTAL1;
            int i0 = lo / 1369;
            int i1 = (hi - 1) / 1369;
            int mask = 0;
            s_img[0] = i0; s_img[1] = i1;
            if (i0 == i1) {
                int c = hi - lo;
                if (atomicAdd(&g_imgcnt[i0], c) + c == 1369) mask |= 1;
            } else {
                int c0 = (i0 + 1) * 1369 - lo;
                int c1 = hi - i1 * 1369;
                if (atomicAdd(&g_imgcnt[i0], c0) + c0 == 1369) mask |= 1;
                if (atomicAdd(&g_imgcnt[i1], c1) + c1 == 1369) mask |= 2;
            }
            s_do = mask;
        }
        __syncthreads();
        int doMask = s_do;
        if (doMask == 0) return;
        __threadfence();                     // acquire contributors' h1

#pragma unroll
        for (int k = 0; k < 2; k++) {
            if (doMask & (1 << k)) {
                const int img = s_img[k];
                for (int posn = t; posn < 324; posn += 256) {
                    int pool = posn / 9, cp = posn - pool * 9;
                    int py = pool / 6, px = pool - py * 6;
                    int cy = 3 * py + cp / 3;
                    int cx = 3 * px + cp % 3;
                    const float* src = g_h1 + (size_t)img * H1S
                                            + (2 * cy) * 37 + 2 * cx;
                    float v[27];
#pragma unroll
                    for (int ic = 0; ic < 3; ic++)
#pragma unroll
                        for (int ky = 0; ky < 3; ky++)
#pragma unroll
                            for (int kx = 0; kx < 3; kx++)
                                v[ic * 9 + ky * 3 + kx] =
                                    __ldg(src + ic * 1369 + ky * 37 + kx);
                    float s = __ldg(c2b);
#pragma unroll
                    for (int i = 0; i < 27; i++) s += v[i] * sw2[i];
                    s_conv[pool][cp] = s;
                }
                __syncthreads();
                if (t < 36) {
                    float m = s_conv[t][0];
#pragma unroll
                    for (int p = 1; p < 9; p++) m = fmaxf(m, s_conv[t][p]);
                    s_hs[t] = fmaxf(m, 0.0f);
                }
                __syncthreads();
                if (t < 6) {
                    float s = __ldg(lb + t);
#pragma unroll
                    for (int i = 0; i < 36; i++)
                        s += s_hs[i] * __ldg(lw + i * 6 + t);
                    g_feat[img * 6 + t] = s;
                }
                __threadfence();
                __syncthreads();
                if (t == 0) atomicAdd(&g_scnt[img / 20], 1);
                __syncthreads();
            }
        }
    }
}

// ---------------------------------------------------------------------------
extern "C" void kernel_launch(void* const* d_in, const int* in_sizes, int n_in,
                              void* d_out, int out_size)
{
    const float* nodes   = (const float*)d_in[0];
    const float* pos     = (const float*)d_in[1];
    const float* attmap  = (const float*)d_in[2];
    const float* conv1_w = (const float*)d_in[4];
    const float* conv1_b = (const float*)d_in[5];
    const float* conv2_w = (const float*)d_in[6];
    const float* conv2_b = (const float*)d_in[7];
    const float* lin_w   = (const float*)d_in[8];
    const float* lin_b   = (const float*)d_in[9];
    const float* wfc_w   = (const float*)d_in[10];
    const float* wfc_b   = (const float*)d_in[11];
    const float* fm_w    = (const float*)d_in[12];
    const float* fm_b    = (const float*)d_in[13];
    const float* lm_w    = (const float*)d_in[14];
    const float* lm_b    = (const float*)d_in[15];
    const float* fc1_w   = (const float*)d_in[16];
    const float* fc1_b   = (const float*)d_in[17];
    const float* fc2_w   = (const float*)d_in[18];
    const float* fc2_b   = (const float*)d_in[19];
    const float* fc3_w   = (const float*)d_in[20];
    const float* fc3_b   = (const float*)d_in[21];
    float* out = (float*)d_out;

    fused_kernel<<<NRD + NCONV, 256>>>(nodes, pos, attmap,
                                       conv1_w, conv1_b, conv2_w, conv2_b,
                                       lin_w, lin_b, wfc_w, wfc_b, fm_w, fm_b,
                                       lm_w, lm_b, fc1_w, fc1_b, fc2_w, fc2_b,
                                       fc3_w, fc3_b, out);
}